// round 16
// baseline (speedup 1.0000x reference)
#include <cuda_runtime.h>
#define FULLMASK 0xffffffffu
typedef unsigned long long u64;

__device__ __forceinline__ u64 ffma2(u64 a, u64 b, u64 c) {
    u64 r; asm("fma.rn.f32x2 %0, %1, %2, %3;" : "=l"(r) : "l"(a), "l"(b), "l"(c)); return r;
}
__device__ __forceinline__ u64 dup2f(float v) {
    u64 r; asm("mov.b64 %0, {%1, %1};" : "=l"(r) : "f"(v)); return r;
}
__device__ __forceinline__ float2 unpk(u64 p) {
    float2 f; asm("mov.b64 {%0, %1}, %2;" : "=f"(f.x), "=f"(f.y) : "l"(p)); return f;
}
#define PBAR(id) asm volatile("bar.sync %0, %1;" :: "r"(id), "r"(64) : "memory")

#define W2_STRIDE 260
#define W1T_STRIDE 20
#define W1R_STRIDE 68
#define HW_STRIDE 68
#define UD_STRIDE 20
#define TS 20
#define TILE 328

#define W2S_OFF 0             // 16640
#define W1T_OFF 16640         // 1280
#define W1R_OFF 17920         // 1088
#define B1S_OFF 19008         // 64
#define B2S_OFF 19072         // 256
#define HW_OFF  19328         // 64*68 = 4352
#define HTS_OFF 23680         // 8 pairs * 512 = 4096
#define VTT_OFF 27776         // 8 pairs * 128 = 1024
#define STS_OFF 28800         // 1024
#define USC_OFF 29824         // 64*20 = 1280
#define DSC_OFF 31104         // 1280
#define TILES_OFF 32384       // 64*328 = 20992
#define SMEM_FLOATS 53376
#define SMEM_BYTES (SMEM_FLOATS * 4)   // 213504

// Warp-pair (2 warps, 8 points) cooperative eval. lane=(g,sub); own point lp.
__device__ __noinline__ float2 geo_dv(float xe0, float xe1, float ve0, float ve1,
                                      int lane, int sub, int g, int warp, int barid)
{
    extern __shared__ float smem[];
    const float* W2s = smem + W2S_OFF;
    const float* W1t = smem + W1T_OFF;
    const float* W1r = smem + W1R_OFF;
    const float* b1s = smem + B1S_OFF;
    const float* b2s = smem + B2S_OFF;
    float* hw = smem + HW_OFF;
    const int pair = warp >> 1;
    const int wside = warp & 1;
    const int pt8 = wside * 4 + g;
    const int lp = warp * 4 + g;
    float* hts = smem + HTS_OFF + pair * 512;   // [c*8+pt]
    float* vtT = smem + VTT_OFF + pair * 128;   // [p*8+pt]
    float* stS = smem + STS_OFF + pair * 128;   // [q*8+pt]
    float* usc = smem + USC_OFF;
    float* dsc = smem + DSC_OFF;
    float* tilesP = smem + TILES_OFF + pair * 8 * TILE;
    const int gbase = lane & 24;

    vtT[sub * 8 + pt8] = ve0;
    vtT[(sub + 8) * 8 + pt8] = ve1;

    float x[16], v[16];
#pragma unroll
    for (int a = 0; a < 8; a++) {
        x[a]     = __shfl_sync(FULLMASK, xe0, gbase + a);
        x[a + 8] = __shfl_sync(FULLMASK, xe1, gbase + a);
        v[a]     = __shfl_sync(FULLMASK, ve0, gbase + a);
        v[a + 8] = __shfl_sync(FULLMASK, ve1, gbase + a);
    }

    // hidden layer: lane owns c = sub+8j of own point
#pragma unroll
    for (int j = 0; j < 8; j++) {
        const int c = sub + 8 * j;
        float pre = b1s[c];
        const float4* wr = (const float4*)(W1t + c * W1T_STRIDE);
#pragma unroll
        for (int t = 0; t < 4; t++) {
            const float4 w = wr[t];
            pre = fmaf(w.x, x[4 * t + 0], pre);
            pre = fmaf(w.y, x[4 * t + 1], pre);
            pre = fmaf(w.z, x[4 * t + 2], pre);
            pre = fmaf(w.w, x[4 * t + 3], pre);
        }
        hts[c * 8 + pt8] = tanhf(pre);
    }
    PBAR(barid);   // h, v pair-visible; prev-eval readers done

    // A-pass: warp covers flat cols [wside*128, +128) for all 8 pair points
    {
        const int cbase = wside * 128 + 4 * lane;
        u64 acc[8][2];
        const ulonglong2 bz = *(const ulonglong2*)(b2s + cbase);
#pragma unroll
        for (int pt = 0; pt < 8; pt++) { acc[pt][0] = bz.x; acc[pt][1] = bz.y; }
        const float* w2c = W2s + cbase;
#pragma unroll 4
        for (int r = 0; r < 64; r++) {
            const float4 hA = *(const float4*)(hts + r * 8);
            const float4 hB = *(const float4*)(hts + r * 8 + 4);
            const ulonglong2 w = *(const ulonglong2*)(w2c + r * W2_STRIDE);
            u64 hd;
            hd = dup2f(hA.x); acc[0][0] = ffma2(hd, w.x, acc[0][0]); acc[0][1] = ffma2(hd, w.y, acc[0][1]);
            hd = dup2f(hA.y); acc[1][0] = ffma2(hd, w.x, acc[1][0]); acc[1][1] = ffma2(hd, w.y, acc[1][1]);
            hd = dup2f(hA.z); acc[2][0] = ffma2(hd, w.x, acc[2][0]); acc[2][1] = ffma2(hd, w.y, acc[2][1]);
            hd = dup2f(hA.w); acc[3][0] = ffma2(hd, w.x, acc[3][0]); acc[3][1] = ffma2(hd, w.y, acc[3][1]);
            hd = dup2f(hB.x); acc[4][0] = ffma2(hd, w.x, acc[4][0]); acc[4][1] = ffma2(hd, w.y, acc[4][1]);
            hd = dup2f(hB.y); acc[5][0] = ffma2(hd, w.x, acc[5][0]); acc[5][1] = ffma2(hd, w.y, acc[5][1]);
            hd = dup2f(hB.z); acc[6][0] = ffma2(hd, w.x, acc[6][0]); acc[6][1] = ffma2(hd, w.y, acc[6][1]);
            hd = dup2f(hB.w); acc[7][0] = ffma2(hd, w.x, acc[7][0]); acc[7][1] = ffma2(hd, w.y, acc[7][1]);
        }
        const int prow = 8 * wside + (lane >> 2);
        const int qcol = 4 * (lane & 3);
#pragma unroll
        for (int pt = 0; pt < 8; pt++)
            *(ulonglong2*)(tilesP + pt * TILE + prow * TS + qcol) =
                make_ulonglong2(acc[pt][0], acc[pt][1]);
    }
    PBAR(barid);   // all 8 tiles complete

    // s = A^T v (own point)
    {
        const float* myt = tilesP + pt8 * TILE;
        float s0 = 0.0f, s1 = 0.0f;
#pragma unroll
        for (int p = 0; p < 16; p++) {
            s0 = fmaf(myt[p * TS + sub], v[p], s0);
            s1 = fmaf(myt[p * TS + sub + 8], v[p], s1);
        }
        stS[sub * 8 + pt8] = s0;
        stS[(sub + 8) * 8 + pt8] = s1;
    }
    PBAR(barid);   // s visible for all 8 points

    // m-pass: lane owns W2 row crow for ALL 8 pair points
    {
        const int crow = wside * 32 + lane;
        const float* R = W2s + crow * W2_STRIDE;
        u64 mp[4] = {0, 0, 0, 0};
#pragma unroll
        for (int ch = 0; ch < 4; ch++) {
            u64 sq[4][4];
#pragma unroll
            for (int qi = 0; qi < 4; qi++) {
                const ulonglong2 sa = *(const ulonglong2*)(stS + (4 * ch + qi) * 8);
                const ulonglong2 sb = *(const ulonglong2*)(stS + (4 * ch + qi) * 8 + 4);
                sq[qi][0] = sa.x; sq[qi][1] = sa.y;
                sq[qi][2] = sb.x; sq[qi][3] = sb.y;
            }
#pragma unroll
            for (int p = 0; p < 16; p++) {
                const float4 w4 = *(const float4*)(R + 16 * p + 4 * ch);
                const ulonglong2 va = *(const ulonglong2*)(vtT + p * 8);
                const ulonglong2 vb = *(const ulonglong2*)(vtT + p * 8 + 4);
                u64 d0 = 0, d1 = 0, d2 = 0, d3 = 0, wd;
                wd = dup2f(w4.x);
                d0 = ffma2(wd, sq[0][0], d0); d1 = ffma2(wd, sq[0][1], d1);
                d2 = ffma2(wd, sq[0][2], d2); d3 = ffma2(wd, sq[0][3], d3);
                wd = dup2f(w4.y);
                d0 = ffma2(wd, sq[1][0], d0); d1 = ffma2(wd, sq[1][1], d1);
                d2 = ffma2(wd, sq[1][2], d2); d3 = ffma2(wd, sq[1][3], d3);
                wd = dup2f(w4.z);
                d0 = ffma2(wd, sq[2][0], d0); d1 = ffma2(wd, sq[2][1], d1);
                d2 = ffma2(wd, sq[2][2], d2); d3 = ffma2(wd, sq[2][3], d3);
                wd = dup2f(w4.w);
                d0 = ffma2(wd, sq[3][0], d0); d1 = ffma2(wd, sq[3][1], d1);
                d2 = ffma2(wd, sq[3][2], d2); d3 = ffma2(wd, sq[3][3], d3);
                mp[0] = ffma2(va.x, d0, mp[0]);
                mp[1] = ffma2(va.y, d1, mp[1]);
                mp[2] = ffma2(vb.x, d2, mp[2]);
                mp[3] = ffma2(vb.y, d3, mp[3]);
            }
        }
        const float4 hA = *(const float4*)(hts + crow * 8);
        const float4 hB = *(const float4*)(hts + crow * 8 + 4);
        const float hv[8] = {hA.x, hA.y, hA.z, hA.w, hB.x, hB.y, hB.z, hB.w};
#pragma unroll
        for (int pp = 0; pp < 4; pp++) {
            const float2 mf = unpk(mp[pp]);
            const int p0 = 2 * pp, p1 = 2 * pp + 1;
            const float th0 = fmaf(-hv[p0], hv[p0], 1.0f);
            const float th1 = fmaf(-hv[p1], hv[p1], 1.0f);
            hw[(pair * 8 + p0) * HW_STRIDE + crow] = 2.0f * th0 * mf.x;
            hw[(pair * 8 + p1) * HW_STRIDE + crow] = 2.0f * th1 * mf.y;
        }
    }
    PBAR(barid);   // w complete (both row halves)

    // u rows sub, sub+8 of own point
    {
        u64 u0p = 0, u1p = 0;
        const float* wc = hw + lp * HW_STRIDE;
        const float* r0 = W1r + sub * W1R_STRIDE;
        const float* r1 = W1r + (sub + 8) * W1R_STRIDE;
#pragma unroll
        for (int t = 0; t < 16; t++) {
            const ulonglong2 cc = *(const ulonglong2*)(wc + 4 * t);
            const ulonglong2 w0 = *(const ulonglong2*)(r0 + 4 * t);
            const ulonglong2 w1 = *(const ulonglong2*)(r1 + 4 * t);
            u0p = ffma2(w0.x, cc.x, u0p); u0p = ffma2(w0.y, cc.y, u0p);
            u1p = ffma2(w1.x, cc.x, u1p); u1p = ffma2(w1.y, cc.y, u1p);
        }
        const float2 f0 = unpk(u0p);
        const float2 f1 = unpk(u1p);
        usc[lp * UD_STRIDE + sub] = f0.x + f0.y;
        usc[lp * UD_STRIDE + sub + 8] = f1.x + f1.y;
    }
    __syncwarp();

    // g-build + interleaved dual SPD solve (own warp's 4 points)
    const int half = lane >> 4;
    const int i16 = lane & 15;
    {
        const float* TA = tilesP + (wside * 4 + half) * TILE;
        const float* TB = tilesP + (wside * 4 + 2 + half) * TILE;
        float growA[16], growB[16];
        {
            u64 ar2[8];
#pragma unroll
            for (int t = 0; t < 4; t++) {
                const ulonglong2 w = *(const ulonglong2*)(TA + i16 * TS + 4 * t);
                ar2[2 * t] = w.x; ar2[2 * t + 1] = w.y;
            }
#pragma unroll
            for (int jr = 0; jr < 16; jr++) {
                u64 gp = 0;
#pragma unroll
                for (int t = 0; t < 4; t++) {
                    const ulonglong2 w = *(const ulonglong2*)(TA + jr * TS + 4 * t);
                    gp = ffma2(ar2[2 * t], w.x, gp);
                    gp = ffma2(ar2[2 * t + 1], w.y, gp);
                }
                const float2 gf = unpk(gp);
                growA[jr] = gf.x + gf.y + ((jr == i16) ? 1.0f : 0.0f);
            }
#pragma unroll
            for (int t = 0; t < 4; t++) {
                const ulonglong2 w = *(const ulonglong2*)(TB + i16 * TS + 4 * t);
                ar2[2 * t] = w.x; ar2[2 * t + 1] = w.y;
            }
#pragma unroll
            for (int jr = 0; jr < 16; jr++) {
                u64 gp = 0;
#pragma unroll
                for (int t = 0; t < 4; t++) {
                    const ulonglong2 w = *(const ulonglong2*)(TB + jr * TS + 4 * t);
                    gp = ffma2(ar2[2 * t], w.x, gp);
                    gp = ffma2(ar2[2 * t + 1], w.y, gp);
                }
                const float2 gf = unpk(gp);
                growB[jr] = gf.x + gf.y + ((jr == i16) ? 1.0f : 0.0f);
            }
        }
        float rhsA = usc[(warp * 4 + half) * UD_STRIDE + i16];
        float rhsB = usc[(warp * 4 + 2 + half) * UD_STRIDE + i16];
#pragma unroll
        for (int k = 0; k < 15; k++) {
            const float pivA = __shfl_sync(FULLMASK, growA[k], k, 16);
            const float pivB = __shfl_sync(FULLMASK, growB[k], k, 16);
            const float prA = __shfl_sync(FULLMASK, rhsA, k, 16);
            const float prB = __shfl_sync(FULLMASK, rhsB, k, 16);
            const float facA = growA[k] * __fdividef(1.0f, pivA);
            const float facB = growB[k] * __fdividef(1.0f, pivB);
            const bool act = (i16 > k);
#pragma unroll
            for (int q = k + 1; q < 16; q++) {
                const float pqA = __shfl_sync(FULLMASK, growA[q], k, 16);
                const float pqB = __shfl_sync(FULLMASK, growB[q], k, 16);
                if (act) {
                    growA[q] = fmaf(-facA, pqA, growA[q]);
                    growB[q] = fmaf(-facB, pqB, growB[q]);
                }
            }
            if (act) {
                rhsA = fmaf(-facA, prA, rhsA);
                rhsB = fmaf(-facB, prB, rhsB);
            }
        }
        float dvlA = 0.0f, dvlB = 0.0f;
#pragma unroll
        for (int k = 15; k >= 0; k--) {
            const float numA = __shfl_sync(FULLMASK, rhsA, k, 16);
            const float numB = __shfl_sync(FULLMASK, rhsB, k, 16);
            const float denA = __shfl_sync(FULLMASK, growA[k], k, 16);
            const float denB = __shfl_sync(FULLMASK, growB[k], k, 16);
            const float ykA = __fdividef(numA, denA);
            const float ykB = __fdividef(numB, denB);
            if (i16 < k) {
                rhsA = fmaf(-growA[k], ykA, rhsA);
                rhsB = fmaf(-growB[k], ykB, rhsB);
            }
            if (i16 == k) { dvlA = -0.5f * ykA; dvlB = -0.5f * ykB; }
        }
        dsc[(warp * 4 + half) * UD_STRIDE + i16] = dvlA;
        dsc[(warp * 4 + 2 + half) * UD_STRIDE + i16] = dvlB;
    }
    __syncwarp();

    float2 res;
    res.x = dsc[lp * UD_STRIDE + sub];
    res.y = dsc[lp * UD_STRIDE + sub + 8];
    return res;
}

__global__ __launch_bounds__(512, 1)
void NeuralGeodesicFlows_45784351375900_kernel(
    const float* __restrict__ z_in, const float* __restrict__ t_ptr,
    const float* __restrict__ W1, const float* __restrict__ b1,
    const float* __restrict__ W2, const float* __restrict__ b2,
    const int* __restrict__ ns_ptr, float* __restrict__ z_out, int B)
{
    extern __shared__ float smem[];
    const int tid = threadIdx.x;

    for (int idx = tid; idx < 64 * 256; idx += 512)
        smem[W2S_OFF + (idx >> 8) * W2_STRIDE + (idx & 255)] = W2[idx];
    for (int idx = tid; idx < 16 * 64; idx += 512) {
        const int a = idx >> 6, c = idx & 63;
        const float w = W1[idx];
        smem[W1R_OFF + a * W1R_STRIDE + c] = w;
        smem[W1T_OFF + c * W1T_STRIDE + a] = w;
    }
    if (tid < 64) smem[B1S_OFF + tid] = b1[tid];
    if (tid < 256) smem[B2S_OFF + tid] = b2[tid];
    __syncthreads();

    const int warp = tid >> 5;
    const int lane = tid & 31;
    const int sub = lane & 7;
    const int g = lane >> 3;
    const int barid = (warp >> 1) + 1;
    int point = blockIdx.x * 64 + warp * 4 + g;
    if (point >= B) point = B - 1;   // clamp: uniform barrier participation

    const float* zp = z_in + point * 32;
    float xs0 = zp[sub];
    float xs1 = zp[sub + 8];
    float vs0 = zp[16 + sub];
    float vs1 = zp[24 + sub];

    const float t = *t_ptr;
    const int ns = *ns_ptr;
    const float dt = t / (float)ns;
    const float hdt = 0.5f * dt;
    const float dt6 = dt * (1.0f / 6.0f);

    for (int s = 0; s < ns; s++) {
        const float2 a1 = geo_dv(xs0, xs1, vs0, vs1, lane, sub, g, warp, barid);
        const float v20 = fmaf(hdt, a1.x, vs0);
        const float v21 = fmaf(hdt, a1.y, vs1);
        const float2 a2 = geo_dv(fmaf(hdt, vs0, xs0), fmaf(hdt, vs1, xs1),
                                 v20, v21, lane, sub, g, warp, barid);
        const float v30 = fmaf(hdt, a2.x, vs0);
        const float v31 = fmaf(hdt, a2.y, vs1);
        const float2 a3 = geo_dv(fmaf(hdt, v20, xs0), fmaf(hdt, v21, xs1),
                                 v30, v31, lane, sub, g, warp, barid);
        const float v40 = fmaf(dt, a3.x, vs0);
        const float v41 = fmaf(dt, a3.y, vs1);
        const float2 a4 = geo_dv(fmaf(dt, v30, xs0), fmaf(dt, v31, xs1),
                                 v40, v41, lane, sub, g, warp, barid);
        xs0 = fmaf(dt6, vs0 + 2.0f * v20 + 2.0f * v30 + v40, xs0);
        xs1 = fmaf(dt6, vs1 + 2.0f * v21 + 2.0f * v31 + v41, xs1);
        vs0 = fmaf(dt6, a1.x + 2.0f * a2.x + 2.0f * a3.x + a4.x, vs0);
        vs1 = fmaf(dt6, a1.y + 2.0f * a2.y + 2.0f * a3.y + a4.y, vs1);
    }

    float* op = z_out + point * 32;
    op[sub] = xs0;
    op[sub + 8] = xs1;
    op[16 + sub] = vs0;
    op[24 + sub] = vs1;
}

extern "C" void kernel_launch(void* const* d_in, const int* in_sizes, int n_in,
                              void* d_out, int out_size)
{
    const float* z  = (const float*)d_in[0];
    const float* t  = (const float*)d_in[1];
    const float* W1 = (const float*)d_in[2];
    const float* b1 = (const float*)d_in[3];
    const float* W2 = (const float*)d_in[4];
    const float* b2 = (const float*)d_in[5];
    const int*   ns = (const int*)d_in[6];
    float* out = (float*)d_out;

    const int B = in_sizes[0] / 32;
    const int grid = (B + 63) / 64;

    cudaFuncSetAttribute(NeuralGeodesicFlows_45784351375900_kernel,
                         cudaFuncAttributeMaxDynamicSharedMemorySize, SMEM_BYTES);
    NeuralGeodesicFlows_45784351375900_kernel<<<grid, 512, SMEM_BYTES>>>(
        z, t, W1, b1, W2, b2, ns, out, B);
}